// round 4
// baseline (speedup 1.0000x reference)
#include <cuda_runtime.h>
#include <cstdint>

#define T_STEPS 5
#define NN 100000
#define DD 64
#define EE 400000

#define M_TOT (T_STEPS * NN)            // 500000 (t,node) rows
#define CHUNK 4096
#define NCHUNK ((M_TOT + CHUNK - 1) / CHUNK)  // 123

// ---------------- device scratch (static globals: allocation-free) ----------
__device__ float g_A[(size_t)T_STEPS * NN * DD];   // x @ W_top  (128 MB)
__device__ float g_B[(size_t)T_STEPS * NN * DD];   // x @ W_bot  (128 MB)
__device__ int   g_cnt[M_TOT];
__device__ int   g_rowptr[M_TOT];
__device__ int   g_cursor[M_TOT];
__device__ int   g_sdst[(size_t)T_STEPS * EE];     // dst sorted by (t,src)
__device__ int   g_chunksum[NCHUNK];
__device__ int   g_chunkoff[NCHUNK];
__device__ float g_w[T_STEPS];

// ---------------- tiny kernels ---------------------------------------------
__global__ void k_zero_cnt() {
    int i = blockIdx.x * blockDim.x + threadIdx.x;
    if (i < M_TOT) g_cnt[i] = 0;
}

__global__ void k_softmax(const float* __restrict__ ea) {
    if (threadIdx.x == 0) {
        float m = ea[0];
        for (int t = 1; t < T_STEPS; t++) m = fmaxf(m, ea[t]);
        float s = 0.f, e[T_STEPS];
        for (int t = 0; t < T_STEPS; t++) { e[t] = __expf(ea[t] - m); s += e[t]; }
        for (int t = 0; t < T_STEPS; t++) g_w[t] = e[t] / s;
    }
}

__global__ void k_hist(const int* __restrict__ edges) {
    int i = blockIdx.x * blockDim.x + threadIdx.x;
    if (i >= T_STEPS * EE) return;
    int t = i / EE, e = i - t * EE;
    int src = edges[(size_t)t * 2 * EE + e];
    atomicAdd(&g_cnt[t * NN + src], 1);
}

__global__ void k_scan1() {
    __shared__ int sh[256];
    int c = blockIdx.x, tid = threadIdx.x;
    int base = c * CHUNK;
    int s = 0;
    for (int i = tid; i < CHUNK; i += 256) {
        int idx = base + i;
        if (idx < M_TOT) s += g_cnt[idx];
    }
    sh[tid] = s; __syncthreads();
    for (int off = 128; off > 0; off >>= 1) {
        if (tid < off) sh[tid] += sh[tid + off];
        __syncthreads();
    }
    if (tid == 0) g_chunksum[c] = sh[0];
}

__global__ void k_scan2() {
    if (threadIdx.x == 0) {
        int run = 0;
        for (int c = 0; c < NCHUNK; c++) { g_chunkoff[c] = run; run += g_chunksum[c]; }
    }
}

__global__ void k_scan3() {
    __shared__ int sh[256];
    int c = blockIdx.x, tid = threadIdx.x;
    int base = c * CHUNK + tid * 16;
    int v[16];
    int s = 0;
    #pragma unroll
    for (int i = 0; i < 16; i++) {
        int idx = base + i;
        int cv = (idx < M_TOT) ? g_cnt[idx] : 0;
        v[i] = s; s += cv;
    }
    sh[tid] = s; __syncthreads();
    // inclusive Hillis-Steele
    for (int off = 1; off < 256; off <<= 1) {
        int add = (tid >= off) ? sh[tid - off] : 0;
        __syncthreads();
        sh[tid] += add;
        __syncthreads();
    }
    int texcl = ((tid > 0) ? sh[tid - 1] : 0) + g_chunkoff[c];
    #pragma unroll
    for (int i = 0; i < 16; i++) {
        int idx = base + i;
        if (idx < M_TOT) {
            int o = texcl + v[i];
            g_rowptr[idx] = o;
            g_cursor[idx] = o;
        }
    }
}

__global__ void k_scatter(const int* __restrict__ edges) {
    int i = blockIdx.x * blockDim.x + threadIdx.x;
    if (i >= T_STEPS * EE) return;
    int t = i / EE, e = i - t * EE;
    int src = edges[(size_t)t * 2 * EE + e];
    int dst = edges[(size_t)t * 2 * EE + EE + e];
    int pos = atomicAdd(&g_cursor[t * NN + src], 1);
    g_sdst[pos] = dst;
}

// ---------------- GEMM: A[t] = x @ W[t][0:64,:], B[t] = x @ W[t][64:128,:] --
// Block tile: 128 nodes x 128 outputs (j<64 -> A, j>=64 -> B), k = 64 (full).
// Thread micro-tile 8x8 via interleaved {4nr..}+{64+4nr..} x {4jc..}+{64+4jc..}
#define XS_STRIDE 132
__global__ void __launch_bounds__(256, 2) k_gemm(const float* __restrict__ x,
                                                 const float* __restrict__ W) {
    extern __shared__ float smem[];
    float* ws = smem;              // [64][128]
    float* xs = smem + 64 * 128;   // [64][XS_STRIDE] transposed x tile

    int t  = blockIdx.y;
    int n0 = blockIdx.x * 128;
    int tid = threadIdx.x;
    const float* Wt = W + (size_t)t * 128 * 64;

    for (int i = tid; i < 64 * 128; i += 256) {
        int k = i >> 7, j = i & 127;
        ws[i] = Wt[(k + ((j >> 6) << 6)) * 64 + (j & 63)];
    }
    for (int i = tid; i < 128 * 64; i += 256) {
        int nl = i >> 6, k = i & 63;
        int n = n0 + nl;
        xs[k * XS_STRIDE + nl] = (n < NN) ? x[(size_t)n * 64 + k] : 0.f;
    }
    __syncthreads();

    int jc = tid & 15, nr = tid >> 4;
    int j0 = jc * 4, nl0 = nr * 4;

    float acc[8][8];
    #pragma unroll
    for (int a = 0; a < 8; a++)
        #pragma unroll
        for (int b = 0; b < 8; b++) acc[a][b] = 0.f;

    #pragma unroll 4
    for (int k = 0; k < 64; k++) {
        float4 xv0 = *(const float4*)&xs[k * XS_STRIDE + nl0];
        float4 xv1 = *(const float4*)&xs[k * XS_STRIDE + 64 + nl0];
        float4 wv0 = *(const float4*)&ws[k * 128 + j0];
        float4 wv1 = *(const float4*)&ws[k * 128 + 64 + j0];
        float xa[8] = {xv0.x, xv0.y, xv0.z, xv0.w, xv1.x, xv1.y, xv1.z, xv1.w};
        float wb[8] = {wv0.x, wv0.y, wv0.z, wv0.w, wv1.x, wv1.y, wv1.z, wv1.w};
        #pragma unroll
        for (int a = 0; a < 8; a++)
            #pragma unroll
            for (int b = 0; b < 8; b++)
                acc[a][b] = fmaf(xa[a], wb[b], acc[a][b]);
    }

    #pragma unroll
    for (int a = 0; a < 8; a++) {
        int nl = (a < 4) ? (nl0 + a) : (64 + nl0 + (a - 4));
        int n = n0 + nl;
        if (n >= NN) continue;
        size_t rowbase = ((size_t)t * NN + n) * 64;
        float4 va = make_float4(acc[a][0], acc[a][1], acc[a][2], acc[a][3]);
        float4 vb = make_float4(acc[a][4], acc[a][5], acc[a][6], acc[a][7]);
        *(float4*)&g_A[rowbase + j0] = va;   // j0..j0+3   < 64 -> A
        *(float4*)&g_B[rowbase + j0] = vb;   // 64+j0..    -> B (store at d=j0)
    }
}

// ---------------- finalize: one warp per node, loops t, reduces edges -------
__global__ void k_finalize(const float* __restrict__ bias,
                           float* __restrict__ out) {
    int gw = (blockIdx.x * blockDim.x + threadIdx.x) >> 5;
    int lane = threadIdx.x & 31;
    if (gw >= NN) return;
    int n = gw;

    float ox = 0.f, oy = 0.f;

    for (int t = 0; t < T_STEPS; t++) {
        int row = t * NN + n;
        int beg = g_rowptr[row];
        int cnt = g_cnt[row];
        float2 a  = *(const float2*)&g_A[(size_t)row * 64 + 2 * lane];
        float2 bi = *(const float2*)&bias[t * 64 + 2 * lane];
        float ax = a.x + bi.x, ay = a.y + bi.y;
        const float* Bt = g_B + (size_t)t * NN * 64;

        float sx = 0.f, sy = 0.f;
        for (int base = 0; base < cnt; base += 32) {
            int m = min(32, cnt - base);
            int d = (lane < m) ? g_sdst[beg + base + lane] : 0;
            int i = 0;
            for (; i + 4 <= m; i += 4) {
                int d0 = __shfl_sync(0xffffffffu, d, i);
                int d1 = __shfl_sync(0xffffffffu, d, i + 1);
                int d2 = __shfl_sync(0xffffffffu, d, i + 2);
                int d3 = __shfl_sync(0xffffffffu, d, i + 3);
                float2 b0 = *(const float2*)&Bt[(size_t)d0 * 64 + 2 * lane];
                float2 b1 = *(const float2*)&Bt[(size_t)d1 * 64 + 2 * lane];
                float2 b2 = *(const float2*)&Bt[(size_t)d2 * 64 + 2 * lane];
                float2 b3 = *(const float2*)&Bt[(size_t)d3 * 64 + 2 * lane];
                sx += fmaxf(ax + b0.x, 0.f); sy += fmaxf(ay + b0.y, 0.f);
                sx += fmaxf(ax + b1.x, 0.f); sy += fmaxf(ay + b1.y, 0.f);
                sx += fmaxf(ax + b2.x, 0.f); sy += fmaxf(ay + b2.y, 0.f);
                sx += fmaxf(ax + b3.x, 0.f); sy += fmaxf(ay + b3.y, 0.f);
            }
            for (; i < m; i++) {
                int di = __shfl_sync(0xffffffffu, d, i);
                float2 bv = *(const float2*)&Bt[(size_t)di * 64 + 2 * lane];
                sx += fmaxf(ax + bv.x, 0.f);
                sy += fmaxf(ay + bv.y, 0.f);
            }
        }
        float scale = g_w[t] / (float)max(cnt, 1);
        ox = fmaf(scale, sx, ox);
        oy = fmaf(scale, sy, oy);
    }
    float2 o = make_float2(ox, oy);
    *(float2*)&out[(size_t)n * 64 + 2 * lane] = o;
}

// ---------------- launch ----------------------------------------------------
extern "C" void kernel_launch(void* const* d_in, const int* in_sizes, int n_in,
                              void* d_out, int out_size) {
    const float* x     = (const float*)d_in[0];  // (N, 64)
    const float* W     = (const float*)d_in[1];  // (T, 128, 64)
    const float* bias  = (const float*)d_in[2];  // (T, 64)
    const float* ea    = (const float*)d_in[3];  // (T,)
    const int*   edges = (const int*)d_in[4];    // (T, 2, E)
    float* out = (float*)d_out;

    (void)in_sizes; (void)n_in; (void)out_size;

    k_zero_cnt<<<(M_TOT + 255) / 256, 256>>>();
    k_softmax<<<1, 32>>>(ea);
    k_hist<<<(T_STEPS * EE + 255) / 256, 256>>>(edges);
    k_scan1<<<NCHUNK, 256>>>();
    k_scan2<<<1, 32>>>();
    k_scan3<<<NCHUNK, 256>>>();
    k_scatter<<<(T_STEPS * EE + 255) / 256, 256>>>(edges);

    static int smem_set = 0;
    int gemm_smem = (64 * 128 + 64 * XS_STRIDE) * sizeof(float);  // 66560 B
    if (!smem_set) {
        cudaFuncSetAttribute(k_gemm, cudaFuncAttributeMaxDynamicSharedMemorySize,
                             gemm_smem);
        smem_set = 1;
    }
    dim3 ggrid((NN + 127) / 128, T_STEPS);
    k_gemm<<<ggrid, 256, gemm_smem>>>(x, W);

    k_finalize<<<(NN * 32 + 255) / 256, 256>>>(bias, out);
}